// round 15
// baseline (speedup 1.0000x reference)
#include <cuda_runtime.h>
#include <cuda_fp16.h>
#include <math.h>
#include <stdint.h>

#define B_   4096
#define T_   32
#define H_   512
#define NG   2048   // 4*H
#define EMB_ 64
#define V_   256
#define O_   64

#define WSCALE 16.0f
#define INV_WSCALE 0.0625f

// ---------------- persistent scratch ----------------
__device__ float d_table[2][V_][NG];            // per-char gate preactivation (+biases), mma-column layout
__device__ __half d_w16[2][NG][H_];             // (W*16) fp16, rows = mma columns, K contiguous
__device__ __half d_hx[2][2][B_ * H_];          // [dir][pp] h (fp16-rounded)
__device__ float d_c[2][B_ * H_];               // cell state, thread-private coalesced layout

// column n (0..2047) -> torch gate row j
__device__ __forceinline__ int jmap2(int n) {
    int gate = (((n >> 3) & 1) << 1) | (n & 1);
    int u    = ((n >> 4) << 2) | ((n >> 1) & 3);
    return gate * H_ + u;
}
__device__ __forceinline__ float sig_f(float x) {
    return __fdividef(1.0f, 1.0f + __expf(-x));
}
__device__ __forceinline__ float tanh_f(float x) {
    return __fdividef(2.0f, 1.0f + __expf(-2.0f * x)) - 1.0f;
}

// ---------------- PTX helpers (plain-target safe) ----------------
__device__ __forceinline__ uint32_t smem_u32(const void* p) {
    uint32_t a;
    asm("{ .reg .u64 t; cvta.to.shared.u64 t, %1; cvt.u32.u64 %0, t; }" : "=r"(a) : "l"(p));
    return a;
}
__device__ __forceinline__ void cp16(uint32_t saddr, const void* g) {
    asm volatile("cp.async.cg.shared.global [%0], [%1], 16;" :: "r"(saddr), "l"(g));
}
#define CP_COMMIT() asm volatile("cp.async.commit_group;" ::: "memory")
#define CP_WAIT(n)  asm volatile("cp.async.wait_group %0;" :: "n"(n) : "memory")

__device__ __forceinline__ void ldsm_x4(uint32_t addr, uint32_t* r) {
    asm volatile("ldmatrix.sync.aligned.m8n8.x4.shared.b16 {%0,%1,%2,%3}, [%4];"
        : "=r"(r[0]), "=r"(r[1]), "=r"(r[2]), "=r"(r[3]) : "r"(addr));
}
__device__ __forceinline__ void mma_f16(float* c, const uint32_t* a, uint32_t b0, uint32_t b1) {
    asm volatile("mma.sync.aligned.m16n8k16.row.col.f32.f16.f16.f32 "
        "{%0,%1,%2,%3}, {%4,%5,%6,%7}, {%8,%9}, {%0,%1,%2,%3};"
        : "+f"(c[0]), "+f"(c[1]), "+f"(c[2]), "+f"(c[3])
        : "r"(a[0]), "r"(a[1]), "r"(a[2]), "r"(a[3]), "r"(b0), "r"(b1));
}

// 128B-row layout, conflict-free swizzle: 16B chunk ^= row&7
__device__ __forceinline__ uint32_t swzoff(int row, int cb) {
    uint32_t off = (uint32_t)(row * 128 + cb);
    return off ^ (uint32_t)((row & 7) << 4);
}

// ---------------- SMEM layout: CTA 128(M)x64(N), K-tile 64, 2 stages, 4 CTAs/SM ----------------
#define TILE_A   16384   // 128 rows x 128B
#define TILE_B   8192    // 64 rows x 128B
#define STG_SZ   24576
#define NSTG     2
#define OFF_A(s)  ((s) * STG_SZ + 0)
#define OFF_B(s)  ((s) * STG_SZ + TILE_A)
#define SMEM_TOTAL (NSTG * STG_SZ)   // 49152
#define HSTG 48                      // h-staging row stride (bytes, 16B-aligned)

// ---------------- one-off precompute ----------------
__global__ void build_table(const float* __restrict__ emb,
                            const float* __restrict__ Wih1, const float* __restrict__ bih1, const float* __restrict__ bhh1,
                            const float* __restrict__ Wih2, const float* __restrict__ bih2, const float* __restrict__ bhh2) {
    int n   = blockIdx.x * 128 + threadIdx.x;
    int v   = blockIdx.y;
    int dir = blockIdx.z;
    const float* Wih = dir ? Wih2 : Wih1;
    const float* bi  = dir ? bih2 : bih1;
    const float* bh  = dir ? bhh2 : bhh1;
    int j = jmap2(n);
    float s = bi[j] + bh[j];
    const float* e = emb + v * EMB_;
    const float* w = Wih + j * EMB_;
#pragma unroll 16
    for (int k = 0; k < EMB_; k++) s += e[k] * w[k];
    d_table[dir][v][n] = s;
}

__global__ void build_wt(const float* __restrict__ Whh1, const float* __restrict__ Whh2) {
    int k   = blockIdx.x * 128 + threadIdx.x;
    int n   = blockIdx.y;
    int dir = blockIdx.z;
    const float* W = dir ? Whh2 : Whh1;
    d_w16[dir][n][k] = __float2half_rn(W[jmap2(n) * H_ + k] * WSCALE);
}

__global__ void init_state() {
    int i = blockIdx.x * 256 + threadIdx.x;
    if (i < B_ * H_) {
        __half z = __float2half_rn(0.f);
        d_hx[0][0][i] = z; d_hx[1][0][i] = z;
        d_c[0][i] = 0.f;   d_c[1][i] = 0.f;
    }
}

// ---------------- async stage: ROWS x 64 fp16 tile = ROWS x 128B (128 threads) ----------------
template<int ROWS>
__device__ __forceinline__ void stage_tile(uint32_t sdst,
                                           const __half* __restrict__ src,
                                           int rowbase, int k0, int tid) {
    constexpr int ITERS = (ROWS * 8) / 128;
#pragma unroll
    for (int j = 0; j < ITERS; j++) {
        int lin = tid + j * 128;
        int row = lin >> 3;
        int c   = lin & 7;
        uint32_t so = (uint32_t)(row * 128 + c * 16);
        so ^= (uint32_t)((row & 7) << 4);
        cp16(sdst + so,
             (const char*)(src + (size_t)(rowbase + row) * H_ + k0) + c * 16);
    }
}

// ---------------- fused recurrent step: single-product fp16 mma, 4 CTAs/SM ----------------
__global__ void __launch_bounds__(128, 4) lstm_step_mma(const int* __restrict__ x, int t, int pp) {
    extern __shared__ __align__(1024) char sm[];
    const int dir  = blockIdx.z;
    const int tcol = dir ? (T_ - 1 - t) : t;
    const int n0   = blockIdx.x * 64;
    const int b0   = blockIdx.y * 128;

    const __half* __restrict__ hx = d_hx[dir][pp];
    __half* __restrict__ hx_n = d_hx[dir][pp ^ 1];
    float* __restrict__ cst = d_c[dir];
    const __half* __restrict__ W = &d_w16[dir][0][0];

    const uint32_t sb = smem_u32(sm);
    const int tid  = threadIdx.x;
    const int wm   = tid >> 5;    // warp 0..3: 32-row band; warp spans all 64 N cols
    const int lane = tid & 31;
    const int g    = lane >> 2;
    const int tg   = lane & 3;
    const int lrow  = lane & 15;
    const int lhalf = lane >> 4;

    // prefetch chars for the epilogue
    int chv[2][2];
#pragma unroll
    for (int i = 0; i < 2; i++) {
        const int r0 = wm * 32 + i * 16 + g;
        chv[i][0] = x[(size_t)(b0 + r0) * T_ + tcol];
        chv[i][1] = x[(size_t)(b0 + r0 + 8) * T_ + tcol];
    }

    // per-thread ldsm offsets (loop-invariant): kk in 0..3 over 128B row
    uint32_t oA[2][4], oB[4][4];
#pragma unroll
    for (int kk = 0; kk < 4; kk++) {
        const int kb = kk * 32 + lhalf * 16;
#pragma unroll
        for (int i = 0; i < 2; i++) oA[i][kk] = swzoff(wm * 32 + i * 16 + lrow, kb);
#pragma unroll
        for (int q = 0; q < 4; q++) oB[q][kk] = swzoff(q * 16 + lrow, kb);
    }

    float acc[2][8][4];
#pragma unroll
    for (int i = 0; i < 2; i++)
#pragma unroll
        for (int j = 0; j < 8; j++)
#pragma unroll
            for (int r = 0; r < 4; r++) acc[i][j][r] = 0.f;

    // prologue: stage k-tile 0
    stage_tile<128>(sb + OFF_A(0), hx, b0, 0, tid);
    stage_tile<64>(sb + OFF_B(0), W,  n0, 0, tid);
    CP_COMMIT();

#pragma unroll
    for (int kt = 0; kt < 8; kt++) {
        CP_WAIT(0);
        __syncthreads();
        if (kt + 1 < 8) {   // stage next tile into the other buffer; overlaps this kt's mma
            const int nb = (kt + 1) & 1;
            const int k0 = (kt + 1) * 64;
            stage_tile<128>(sb + OFF_A(nb), hx, b0, k0, tid);
            stage_tile<64>(sb + OFF_B(nb), W,  n0, k0, tid);
            CP_COMMIT();
        }
        const int buf = kt & 1;
        const uint32_t baseA = sb + OFF_A(buf);
        const uint32_t baseB = sb + OFF_B(buf);
#pragma unroll
        for (int kk = 0; kk < 4; kk++) {
            uint32_t af[2][4], bf4[4][4];
#pragma unroll
            for (int i = 0; i < 2; i++) ldsm_x4(baseA + oA[i][kk], af[i]);
#pragma unroll
            for (int q = 0; q < 4; q++) ldsm_x4(baseB + oB[q][kk], bf4[q]);
#pragma unroll
            for (int i = 0; i < 2; i++)
#pragma unroll
                for (int q = 0; q < 4; q++)
#pragma unroll
                    for (int nb2 = 0; nb2 < 2; nb2++)
                        mma_f16(acc[i][q * 2 + nb2], af[i], bf4[q][nb2], bf4[q][nb2 + 2]);
        }
    }

    __syncthreads();   // all mma smem reads retired before epilogue staging reuse

    // ---------------- epilogue: gates + cell update, in-register ----------------
    const int cbase = (((blockIdx.y * 32 + blockIdx.x) * 128 + tid) << 4);
    float cv[16];
#pragma unroll
    for (int q = 0; q < 4; q++) *(float4*)&cv[q * 4] = *(const float4*)&cst[cbase + q * 4];

#pragma unroll
    for (int i = 0; i < 2; i++) {
        const int r0 = wm * 32 + i * 16 + g;
        const float* trow0 = &d_table[dir][chv[i][0]][n0];
        const float* trow1 = &d_table[dir][chv[i][1]][n0];
#pragma unroll
        for (int jj = 0; jj < 4; jj++) {
            const int colIF = jj * 16 + 2 * tg;
            const int u_l   = jj * 4 + tg;          // local unit 0..15
#pragma unroll
            for (int half = 0; half < 2; half++) {
                const float* trow = half ? trow1 : trow0;
                const float2 tif = *(const float2*)&trow[colIF];
                const float2 tgo = *(const float2*)&trow[colIF + 8];
                float gi = fmaf(INV_WSCALE, acc[i][jj * 2 + 0][half * 2 + 0], tif.x);
                float gf = fmaf(INV_WSCALE, acc[i][jj * 2 + 0][half * 2 + 1], tif.y);
                float gg = fmaf(INV_WSCALE, acc[i][jj * 2 + 1][half * 2 + 0], tgo.x);
                float go = fmaf(INV_WSCALE, acc[i][jj * 2 + 1][half * 2 + 1], tgo.y);
                const int idx = i * 8 + jj * 2 + half;
                float c_new = sig_f(gf) * cv[idx] + sig_f(gi) * tanh_f(gg);
                cv[idx] = c_new;
                const float hv = sig_f(go) * tanh_f(c_new);
                const int rl = r0 + half * 8;
                *(__half*)(sm + rl * HSTG + u_l * 2) = __float2half_rn(hv);
            }
        }
    }
#pragma unroll
    for (int q = 0; q < 4; q++) *(float4*)&cst[cbase + q * 4] = *(const float4*)&cv[q * 4];

    __syncthreads();
    // coalesced h store: 128 rows x 16 units (32B/row), HSTG is 16B-aligned
    const int u0 = blockIdx.x * 16;
    {
        const int row = tid;
        uint4 v0 = *(const uint4*)(sm + row * HSTG);
        uint4 v1 = *(const uint4*)(sm + row * HSTG + 16);
        char* dst = (char*)(hx_n + (size_t)(b0 + row) * H_ + u0);
        *(uint4*)dst = v0;
        *(uint4*)(dst + 16) = v1;
    }
}

// ---------------- classifier head + softmax (tiled: 32 rows / block) ----------------
#define HEAD_ROWS 32
#define HEAD_SMEM (HEAD_ROWS * 1024 * 2 + HEAD_ROWS * 66 * 4)   // 65536 + 8448 = 73984
__global__ void __launch_bounds__(256) head_kernel(const float* __restrict__ Wlin,
                                                   const float* __restrict__ blin,
                                                   float* __restrict__ out) {
    extern __shared__ char hsm[];
    __half* hrow = (__half*)hsm;                           // [32][1024]
    float*  lgs  = (float*)(hsm + HEAD_ROWS * 1024 * 2);   // [32][66]
    const int b0   = blockIdx.x * HEAD_ROWS;
    const int tid  = threadIdx.x;
    const int w    = tid >> 5;
    const int lane = tid & 31;

    // stage h tile: 32 rows x (512 dir0 + 512 dir1) halves
#pragma unroll
    for (int it = 0; it < 8; it++) {
        int idx = tid + it * 256;    // 0..2047
        int r = idx >> 6;            // 64 uint4 per row per dir
        int c = idx & 63;
        *(uint4*)&hrow[r * 1024 + c * 8] =
            *(const uint4*)&d_hx[0][0][(size_t)(b0 + r) * H_ + c * 8];
        *(uint4*)&hrow[r * 1024 + 512 + c * 8] =
            *(const uint4*)&d_hx[1][0][(size_t)(b0 + r) * H_ + c * 8];
    }
    __syncthreads();

    // each warp computes 8 outputs; Wlin row held in registers, reused over 32 rows
#pragma unroll
    for (int oo = 0; oo < 8; oo++) {
        const int o = w * 8 + oo;
        float4 wreg[8];
#pragma unroll
        for (int kk = 0; kk < 8; kk++)
            wreg[kk] = *(const float4*)&Wlin[o * 1024 + kk * 128 + lane * 4];
        const float bo = blin[o];
        for (int r = 0; r < HEAD_ROWS; r++) {
            float s = 0.f;
#pragma unroll
            for (int kk = 0; kk < 8; kk++) {
                const __half2* hp = (const __half2*)&hrow[r * 1024 + kk * 128 + lane * 4];
                float2 h01 = __half22float2(hp[0]);
                float2 h23 = __half22float2(hp[1]);
                s += wreg[kk].x * h01.x + wreg[kk].y * h01.y
                   + wreg[kk].z * h23.x + wreg[kk].w * h23.y;
            }
#pragma unroll
            for (int off = 16; off; off >>= 1) s += __shfl_down_sync(0xffffffffu, s, off);
            if (lane == 0) lgs[r * 66 + o] = s + bo;
        }
    }
    __syncthreads();

    // softmax: 8 warps x 4 rows
#pragma unroll
    for (int rr = 0; rr < 4; rr++) {
        const int r = w * 4 + rr;
        float v0 = lgs[r * 66 + lane];
        float v1 = lgs[r * 66 + 32 + lane];
        float m = fmaxf(v0, v1);
#pragma unroll
        for (int off = 16; off; off >>= 1) m = fmaxf(m, __shfl_xor_sync(0xffffffffu, m, off));
        float e0 = __expf(v0 - m), e1 = __expf(v1 - m);
        float s = e0 + e1;
#pragma unroll
        for (int off = 16; off; off >>= 1) s += __shfl_xor_sync(0xffffffffu, s, off);
        float inv = __fdividef(1.0f, s);
        out[(size_t)(b0 + r) * O_ + lane]      = e0 * inv;
        out[(size_t)(b0 + r) * O_ + 32 + lane] = e1 * inv;
    }
}

// ---------------- launch ----------------
extern "C" void kernel_launch(void* const* d_in, const int* in_sizes, int n_in,
                              void* d_out, int out_size) {
    const int*   x    = (const int*)d_in[0];
    const float* emb  = (const float*)d_in[2];
    const float* Wih1 = (const float*)d_in[3];
    const float* Whh1 = (const float*)d_in[4];
    const float* bih1 = (const float*)d_in[5];
    const float* bhh1 = (const float*)d_in[6];
    const float* Wih2 = (const float*)d_in[7];
    const float* Whh2 = (const float*)d_in[8];
    const float* bih2 = (const float*)d_in[9];
    const float* bhh2 = (const float*)d_in[10];
    const float* Wlin = (const float*)d_in[11];
    const float* blin = (const float*)d_in[12];
    float* out = (float*)d_out;

    cudaFuncSetAttribute(lstm_step_mma, cudaFuncAttributeMaxDynamicSharedMemorySize, SMEM_TOTAL);
    cudaFuncSetAttribute(head_kernel,   cudaFuncAttributeMaxDynamicSharedMemorySize, HEAD_SMEM);

    dim3 g1(NG / 128, V_, 2);
    build_table<<<g1, 128>>>(emb, Wih1, bih1, bhh1, Wih2, bih2, bhh2);
    dim3 g2(H_ / 128, NG, 2);
    build_wt<<<g2, 128>>>(Whh1, Whh2);
    init_state<<<(B_ * H_ + 255) / 256, 256>>>();

    dim3 gs(NG / 64, B_ / 128, 2);   // (32, 32, 2) = 2048 CTAs, 4/SM
    for (int t = 0; t < T_; t++) {
        lstm_step_mma<<<gs, 128, SMEM_TOTAL>>>(x, t, t & 1);
    }
    head_kernel<<<B_ / HEAD_ROWS, 256, HEAD_SMEM>>>(Wlin, blin, out);
}

// round 16
// speedup vs baseline: 1.1310x; 1.1310x over previous
#include <cuda_runtime.h>
#include <cuda_fp16.h>
#include <math.h>
#include <stdint.h>

#define B_   4096
#define T_   32
#define H_   512
#define NG   2048   // 4*H
#define EMB_ 64
#define V_   256
#define O_   64

#define WSCALE 16.0f
#define INV_WSCALE 0.0625f

// ---------------- persistent scratch ----------------
__device__ float d_table[2][V_][NG];            // per-char gate preactivation (+biases), mma-column layout
__device__ __half d_w16[2][NG][H_];             // (W*16) fp16, rows = mma columns, K contiguous
__device__ __half d_hx[2][2][B_ * H_];          // [dir][pp] h (fp16-rounded)
__device__ float d_c[2][B_ * H_];               // cell state, thread-private coalesced layout

// column n (0..2047) -> torch gate row j
__device__ __forceinline__ int jmap2(int n) {
    int gate = (((n >> 3) & 1) << 1) | (n & 1);
    int u    = ((n >> 4) << 2) | ((n >> 1) & 3);
    return gate * H_ + u;
}
__device__ __forceinline__ float sig_f(float x) {
    return __fdividef(1.0f, 1.0f + __expf(-x));
}
__device__ __forceinline__ float tanh_f(float x) {
    return __fdividef(2.0f, 1.0f + __expf(-2.0f * x)) - 1.0f;
}

// ---------------- PTX helpers (plain-target safe) ----------------
__device__ __forceinline__ uint32_t smem_u32(const void* p) {
    uint32_t a;
    asm("{ .reg .u64 t; cvta.to.shared.u64 t, %1; cvt.u32.u64 %0, t; }" : "=r"(a) : "l"(p));
    return a;
}
__device__ __forceinline__ void cp16(uint32_t saddr, const void* g) {
    asm volatile("cp.async.cg.shared.global [%0], [%1], 16;" :: "r"(saddr), "l"(g));
}
#define CP_COMMIT() asm volatile("cp.async.commit_group;" ::: "memory")
#define CP_WAIT(n)  asm volatile("cp.async.wait_group %0;" :: "n"(n) : "memory")

__device__ __forceinline__ void ldsm_x4(uint32_t addr, uint32_t* r) {
    asm volatile("ldmatrix.sync.aligned.m8n8.x4.shared.b16 {%0,%1,%2,%3}, [%4];"
        : "=r"(r[0]), "=r"(r[1]), "=r"(r[2]), "=r"(r[3]) : "r"(addr));
}
__device__ __forceinline__ void mma_f16(float* c, const uint32_t* a, uint32_t b0, uint32_t b1) {
    asm volatile("mma.sync.aligned.m16n8k16.row.col.f32.f16.f16.f32 "
        "{%0,%1,%2,%3}, {%4,%5,%6,%7}, {%8,%9}, {%0,%1,%2,%3};"
        : "+f"(c[0]), "+f"(c[1]), "+f"(c[2]), "+f"(c[3])
        : "r"(a[0]), "r"(a[1]), "r"(a[2]), "r"(a[3]), "r"(b0), "r"(b1));
}

// 128B-row layout, conflict-free swizzle: 16B chunk ^= row&7
__device__ __forceinline__ uint32_t swzoff(int row, int cb) {
    uint32_t off = (uint32_t)(row * 128 + cb);
    return off ^ (uint32_t)((row & 7) << 4);
}

// ---------------- SMEM layout: CTA 128x128, K-tile 64, 3 stages ----------------
#define TILE_SZ  16384
#define STG_SZ   32768
#define NSTG     3
#define OFF_A(s)  ((s) * STG_SZ + 0)
#define OFF_B(s)  ((s) * STG_SZ + TILE_SZ)
#define SMEM_TOTAL (NSTG * STG_SZ)   // 98304
#define HSTG 80                      // h-staging row stride (bytes)

// ---------------- one-off precompute ----------------
__global__ void build_table(const float* __restrict__ emb,
                            const float* __restrict__ Wih1, const float* __restrict__ bih1, const float* __restrict__ bhh1,
                            const float* __restrict__ Wih2, const float* __restrict__ bih2, const float* __restrict__ bhh2) {
    int n   = blockIdx.x * 128 + threadIdx.x;
    int v   = blockIdx.y;
    int dir = blockIdx.z;
    const float* Wih = dir ? Wih2 : Wih1;
    const float* bi  = dir ? bih2 : bih1;
    const float* bh  = dir ? bhh2 : bhh1;
    int j = jmap2(n);
    float s = bi[j] + bh[j];
    const float* e = emb + v * EMB_;
    const float* w = Wih + j * EMB_;
#pragma unroll 16
    for (int k = 0; k < EMB_; k++) s += e[k] * w[k];
    d_table[dir][v][n] = s;
}

__global__ void build_wt(const float* __restrict__ Whh1, const float* __restrict__ Whh2) {
    int k   = blockIdx.x * 128 + threadIdx.x;
    int n   = blockIdx.y;
    int dir = blockIdx.z;
    const float* W = dir ? Whh2 : Whh1;
    d_w16[dir][n][k] = __float2half_rn(W[jmap2(n) * H_ + k] * WSCALE);
}

__global__ void init_state() {
    int i = blockIdx.x * 256 + threadIdx.x;
    if (i < B_ * H_) {
        __half z = __float2half_rn(0.f);
        d_hx[0][0][i] = z; d_hx[1][0][i] = z;
        d_c[0][i] = 0.f;   d_c[1][i] = 0.f;
    }
}

// ---------------- async stage: one 128x64 fp16 tile = 128 rows x 128B (256 threads) ----------------
__device__ __forceinline__ void stage_tile(uint32_t sdst,
                                           const __half* __restrict__ src,
                                           int rowbase, int k0, int tid) {
#pragma unroll
    for (int j = 0; j < 4; j++) {
        int lin = tid + j * 256;              // 0..1023
        int row = lin >> 3;                   // 0..127
        int c   = lin & 7;                    // 8 x 16B = 128B per row
        uint32_t so = (uint32_t)(row * 128 + c * 16);
        so ^= (uint32_t)((row & 7) << 4);
        cp16(sdst + so,
             (const char*)(src + (size_t)(rowbase + row) * H_ + k0) + c * 16);
    }
}

// ---------------- fused recurrent step: single-product fp16 mma (R10 geometry) ----------------
__global__ void __launch_bounds__(256, 2) lstm_step_mma(const int* __restrict__ x, int t, int pp) {
    extern __shared__ __align__(1024) char sm[];
    const int dir  = blockIdx.z;
    const int tcol = dir ? (T_ - 1 - t) : t;
    const int n0   = blockIdx.x * 128;
    const int b0   = blockIdx.y * 128;

    const __half* __restrict__ hx = d_hx[dir][pp];
    __half* __restrict__ hx_n = d_hx[dir][pp ^ 1];
    float* __restrict__ cst = d_c[dir];
    const __half* __restrict__ W = &d_w16[dir][0][0];

    const uint32_t sb = smem_u32(sm);
    const int tid  = threadIdx.x;
    const int wid  = tid >> 5;
    const int lane = tid & 31;
    const int wm   = wid >> 1;    // 0..3: 32-row band
    const int wn   = wid & 1;     // 0..1: 64-col band
    const int g    = lane >> 2;
    const int tg   = lane & 3;
    const int lrow  = lane & 15;
    const int lhalf = lane >> 4;

    // prefetch chars for the epilogue
    int chv[2][2];
#pragma unroll
    for (int i = 0; i < 2; i++) {
        const int r0 = wm * 32 + i * 16 + g;
        chv[i][0] = x[(size_t)(b0 + r0) * T_ + tcol];
        chv[i][1] = x[(size_t)(b0 + r0 + 8) * T_ + tcol];
    }

    // per-thread ldsm offsets (loop-invariant): kk in 0..3 over 128B row
    uint32_t oA[2][4], oB[4][4];
#pragma unroll
    for (int kk = 0; kk < 4; kk++) {
        const int kb = kk * 32 + lhalf * 16;
#pragma unroll
        for (int i = 0; i < 2; i++) oA[i][kk] = swzoff(wm * 32 + i * 16 + lrow, kb);
#pragma unroll
        for (int q = 0; q < 4; q++) oB[q][kk] = swzoff(wn * 64 + q * 16 + lrow, kb);
    }

    float acc[2][8][4];
#pragma unroll
    for (int i = 0; i < 2; i++)
#pragma unroll
        for (int j = 0; j < 8; j++)
#pragma unroll
            for (int r = 0; r < 4; r++) acc[i][j][r] = 0.f;

    // prologue: stage k-tiles 0,1
#pragma unroll
    for (int s = 0; s < 2; s++) {
        stage_tile(sb + OFF_A(s), hx, b0, s * 64, tid);
        stage_tile(sb + OFF_B(s), W,  n0, s * 64, tid);
        CP_COMMIT();
    }

#pragma unroll
    for (int kt = 0; kt < 8; kt++) {
        if (kt < 7) { CP_WAIT(1); } else { CP_WAIT(0); }
        __syncthreads();
        if (kt + 2 < 8) {
            const int nb = (kt + 2) % NSTG;
            const int k0 = (kt + 2) * 64;
            stage_tile(sb + OFF_A(nb), hx, b0, k0, tid);
            stage_tile(sb + OFF_B(nb), W,  n0, k0, tid);
            CP_COMMIT();
        }
        const int buf = kt % NSTG;
        const uint32_t baseA = sb + OFF_A(buf);
        const uint32_t baseB = sb + OFF_B(buf);
#pragma unroll
        for (int kk = 0; kk < 4; kk++) {
            uint32_t af[2][4], bf4[4][4];
#pragma unroll
            for (int i = 0; i < 2; i++) ldsm_x4(baseA + oA[i][kk], af[i]);
#pragma unroll
            for (int q = 0; q < 4; q++) ldsm_x4(baseB + oB[q][kk], bf4[q]);
#pragma unroll
            for (int i = 0; i < 2; i++)
#pragma unroll
                for (int q = 0; q < 4; q++)
#pragma unroll
                    for (int nb2 = 0; nb2 < 2; nb2++)
                        mma_f16(acc[i][q * 2 + nb2], af[i], bf4[q][nb2], bf4[q][nb2 + 2]);
        }
    }

    __syncthreads();   // all mma smem reads retired before epilogue staging reuse

    // ---------------- epilogue: gates + cell update, in-register ----------------
    const int cbase = (((blockIdx.y * 16 + blockIdx.x) * 256 + tid) << 4);
    float cv[16];
#pragma unroll
    for (int q = 0; q < 4; q++) *(float4*)&cv[q * 4] = *(const float4*)&cst[cbase + q * 4];

#pragma unroll
    for (int i = 0; i < 2; i++) {
        const int r0 = wm * 32 + i * 16 + g;
        const float* trow0 = &d_table[dir][chv[i][0]][n0];
        const float* trow1 = &d_table[dir][chv[i][1]][n0];
#pragma unroll
        for (int jj = 0; jj < 4; jj++) {
            const int colIF = wn * 64 + jj * 16 + 2 * tg;
            const int u_l   = (wn * 4 + jj) * 4 + tg;
#pragma unroll
            for (int half = 0; half < 2; half++) {
                const float* trow = half ? trow1 : trow0;
                const float2 tif = *(const float2*)&trow[colIF];
                const float2 tgo = *(const float2*)&trow[colIF + 8];
                float gi = fmaf(INV_WSCALE, acc[i][jj * 2 + 0][half * 2 + 0], tif.x);
                float gf = fmaf(INV_WSCALE, acc[i][jj * 2 + 0][half * 2 + 1], tif.y);
                float gg = fmaf(INV_WSCALE, acc[i][jj * 2 + 1][half * 2 + 0], tgo.x);
                float go = fmaf(INV_WSCALE, acc[i][jj * 2 + 1][half * 2 + 1], tgo.y);
                const int idx = i * 8 + jj * 2 + half;
                float c_new = sig_f(gf) * cv[idx] + sig_f(gi) * tanh_f(gg);
                cv[idx] = c_new;
                const float hv = sig_f(go) * tanh_f(c_new);
                const int rl = r0 + half * 8;
                *(__half*)(sm + rl * HSTG + u_l * 2) = __float2half_rn(hv);
            }
        }
    }
#pragma unroll
    for (int q = 0; q < 4; q++) *(float4*)&cst[cbase + q * 4] = *(const float4*)&cv[q * 4];

    __syncthreads();
    // coalesced h store: 128 rows x 32 units (64B/row)
    const int u0 = n0 >> 2;
    {
        const int row = tid >> 1;
        const int q   = tid & 1;
        uint4 v0 = *(const uint4*)(sm + row * HSTG + q * 32);
        uint4 v1 = *(const uint4*)(sm + row * HSTG + q * 32 + 16);
        char* dst = (char*)(hx_n + (size_t)(b0 + row) * H_ + u0) + q * 32;
        *(uint4*)dst = v0;
        *(uint4*)(dst + 16) = v1;
    }
}

// ---------------- classifier head + softmax (tiled: 32 rows / block) ----------------
#define HEAD_ROWS 32
#define HEAD_SMEM (HEAD_ROWS * 1024 * 2 + HEAD_ROWS * 66 * 4)   // 65536 + 8448 = 73984
__global__ void __launch_bounds__(256) head_kernel(const float* __restrict__ Wlin,
                                                   const float* __restrict__ blin,
                                                   float* __restrict__ out) {
    extern __shared__ char hsm[];
    __half* hrow = (__half*)hsm;                           // [32][1024]
    float*  lgs  = (float*)(hsm + HEAD_ROWS * 1024 * 2);   // [32][66]
    const int b0   = blockIdx.x * HEAD_ROWS;
    const int tid  = threadIdx.x;
    const int w    = tid >> 5;
    const int lane = tid & 31;

    // stage h tile: 32 rows x (512 dir0 + 512 dir1) halves
#pragma unroll
    for (int it = 0; it < 8; it++) {
        int idx = tid + it * 256;    // 0..2047
        int r = idx >> 6;            // 64 uint4 per row per dir
        int c = idx & 63;
        *(uint4*)&hrow[r * 1024 + c * 8] =
            *(const uint4*)&d_hx[0][0][(size_t)(b0 + r) * H_ + c * 8];
        *(uint4*)&hrow[r * 1024 + 512 + c * 8] =
            *(const uint4*)&d_hx[1][0][(size_t)(b0 + r) * H_ + c * 8];
    }
    __syncthreads();

    // each warp computes 8 outputs; Wlin row held in registers, reused over 32 rows
#pragma unroll
    for (int oo = 0; oo < 8; oo++) {
        const int o = w * 8 + oo;
        float4 wreg[8];
#pragma unroll
        for (int kk = 0; kk < 8; kk++)
            wreg[kk] = *(const float4*)&Wlin[o * 1024 + kk * 128 + lane * 4];
        const float bo = blin[o];
        for (int r = 0; r < HEAD_ROWS; r++) {
            float s = 0.f;
#pragma unroll
            for (int kk = 0; kk < 8; kk++) {
                const __half2* hp = (const __half2*)&hrow[r * 1024 + kk * 128 + lane * 4];
                float2 h01 = __half22float2(hp[0]);
                float2 h23 = __half22float2(hp[1]);
                s += wreg[kk].x * h01.x + wreg[kk].y * h01.y
                   + wreg[kk].z * h23.x + wreg[kk].w * h23.y;
            }
#pragma unroll
            for (int off = 16; off; off >>= 1) s += __shfl_down_sync(0xffffffffu, s, off);
            if (lane == 0) lgs[r * 66 + o] = s + bo;
        }
    }
    __syncthreads();

    // softmax: 8 warps x 4 rows
#pragma unroll
    for (int rr = 0; rr < 4; rr++) {
        const int r = w * 4 + rr;
        float v0 = lgs[r * 66 + lane];
        float v1 = lgs[r * 66 + 32 + lane];
        float m = fmaxf(v0, v1);
#pragma unroll
        for (int off = 16; off; off >>= 1) m = fmaxf(m, __shfl_xor_sync(0xffffffffu, m, off));
        float e0 = __expf(v0 - m), e1 = __expf(v1 - m);
        float s = e0 + e1;
#pragma unroll
        for (int off = 16; off; off >>= 1) s += __shfl_xor_sync(0xffffffffu, s, off);
        float inv = __fdividef(1.0f, s);
        out[(size_t)(b0 + r) * O_ + lane]      = e0 * inv;
        out[(size_t)(b0 + r) * O_ + 32 + lane] = e1 * inv;
    }
}

// ---------------- launch ----------------
extern "C" void kernel_launch(void* const* d_in, const int* in_sizes, int n_in,
                              void* d_out, int out_size) {
    const int*   x    = (const int*)d_in[0];
    const float* emb  = (const float*)d_in[2];
    const float* Wih1 = (const float*)d_in[3];
    const float* Whh1 = (const float*)d_in[4];
    const float* bih1 = (const float*)d_in[5];
    const float* bhh1 = (const float*)d_in[6];
    const float* Wih2 = (const float*)d_in[7];
    const float* Whh2 = (const float*)d_in[8];
    const float* bih2 = (const float*)d_in[9];
    const float* bhh2 = (const float*)d_in[10];
    const float* Wlin = (const float*)d_in[11];
    const float* blin = (const float*)d_in[12];
    float* out = (float*)d_out;

    cudaFuncSetAttribute(lstm_step_mma, cudaFuncAttributeMaxDynamicSharedMemorySize, SMEM_TOTAL);
    cudaFuncSetAttribute(head_kernel,   cudaFuncAttributeMaxDynamicSharedMemorySize, HEAD_SMEM);

    dim3 g1(NG / 128, V_, 2);
    build_table<<<g1, 128>>>(emb, Wih1, bih1, bhh1, Wih2, bih2, bhh2);
    dim3 g2(H_ / 128, NG, 2);
    build_wt<<<g2, 128>>>(Whh1, Whh2);
    init_state<<<(B_ * H_ + 255) / 256, 256>>>();

    dim3 gs(NG / 128, B_ / 128, 2);   // (16, 32, 2) = 1024 CTAs, 2/SM
    for (int t = 0; t < T_; t++) {
        lstm_step_mma<<<gs, 256, SMEM_TOTAL>>>(x, t, t & 1);
    }
    head_kernel<<<B_ / HEAD_ROWS, 256, HEAD_SMEM>>>(Wlin, blin, out);
}